// round 16
// baseline (speedup 1.0000x reference)
#include <cuda_runtime.h>
#include <cuda_fp16.h>

#define NH 16
#define HD 64
#define BB 2
#define SS 2048
#define DD 1024
#define ND (NH*HD)          // 1024
#define BHSD (BB*NH*SS*HD)

// attn scratch as fp16x2 words, PRE-PERMUTED (round-15 layout, unchanged):
//   Q: [bh][s][32 words, slot16 order], pre-scaled by QSC
//   K: [bh][s][32 words, slot16 order]
//   V: [bh][d][SS/2 words], per-64-key group pi order at slot16 positions
__device__ unsigned g_scr[3][BHSD];

// proj inputs pre-converted:
//   g_ah/g_al: [which][row 4096][kb 64][8 words, slotw order], fp16x2 hi/lo of A
//   g_wt:      [which][n 1024][kb 64][8 words, slotw order], fp16x2 of W^T
// slotw(u) = (u&3)*2 + (u>>2); word u of block kb covers k = kb*16 + 2u, 2u+1
__device__ unsigned g_ah[3][4096 * 512];
__device__ unsigned g_al[3][4096 * 512];
__device__ unsigned g_wt[3][1024 * 512];

#define QSC 0.18033688011112042f          /* 0.125 * log2(e) */
#define CMSK 1.4426950408889634e10f       /* 1e10 * log2(e) */
#define SLOT16(w) ((((w) & 3) << 3) + (((w) >> 3) << 1) + (((w) >> 2) & 1))
#define SLOTW(u)  ((((u) & 3) << 1) + ((u) >> 2))

__device__ __forceinline__ float ex2(float x) {
    float r; asm("ex2.approx.f32 %0, %1;" : "=f"(r) : "f"(x)); return r;
}

__device__ __forceinline__ void mmah(float* c, const unsigned* a, const unsigned* b) {
    asm volatile(
        "mma.sync.aligned.m16n8k16.row.col.f32.f16.f16.f32 "
        "{%0,%1,%2,%3}, {%4,%5,%6,%7}, {%8,%9}, {%0,%1,%2,%3};\n"
        : "+f"(c[0]), "+f"(c[1]), "+f"(c[2]), "+f"(c[3])
        : "r"(a[0]), "r"(a[1]), "r"(a[2]), "r"(a[3]), "r"(b[0]), "r"(b[1]));
}

__device__ __forceinline__ unsigned packh2(float lo, float hi) {
    unsigned r; asm("cvt.rn.f16x2.f32 %0, %1, %2;" : "=r"(r) : "f"(hi), "f"(lo));
    return r;
}
__device__ __forceinline__ void splith2(float2 x, unsigned& h, unsigned& l) {
    h = packh2(x.x, x.y);
    __half2 hh = *(__half2*)&h;
    float2 hf = __half22float2(hh);
    l = packh2(x.x - hf.x, x.y - hf.y);
}

__device__ __forceinline__ void cp16(unsigned smem_addr, const void* gptr) {
    asm volatile("cp.async.cg.shared.global [%0], [%1], 16;"
                 :: "r"(smem_addr), "l"(gptr));
}
#define CP_COMMIT() asm volatile("cp.async.commit_group;" ::: "memory")
#define CP_WAIT0()  asm volatile("cp.async.wait_group 0;" ::: "memory")

// ---------------------------------------------------------------------------
// prep_a: split A (q/k/v) into fp16 hi/lo packed words, slotw order.
// One thread per word: idx = (row*64 + kb)*8 + u.
// ---------------------------------------------------------------------------
__global__ __launch_bounds__(256) void prep_a(
    const float* __restrict__ q, const float* __restrict__ k, const float* __restrict__ v)
{
    const int which = blockIdx.y;
    const float* A = which == 0 ? q : (which == 1 ? k : v);
    unsigned idx = blockIdx.x * 256u + threadIdx.x;   // 0 .. 4096*64*8-1
    int u = idx & 7;
    unsigned blk = idx >> 3;                          // row*64 + kb
    float2 x = *(const float2*)(A + (size_t)(blk >> 6) * DD + (blk & 63) * 16 + 2 * u);
    unsigned h, l;
    splith2(x, h, l);
    unsigned dst = blk * 8 + SLOTW(u);
    g_ah[which][dst] = h;
    g_al[which][dst] = l;
}

// ---------------------------------------------------------------------------
// prep_w: W -> fp16 W^T packed words, slotw order.
// One thread per adjacent slot pair: idx = (n*64 + kb)*4 + tig -> words u=tig, tig+4.
// ---------------------------------------------------------------------------
__global__ __launch_bounds__(256) void prep_w(
    const float* __restrict__ Wq, const float* __restrict__ Wk, const float* __restrict__ Wv)
{
    const int which = blockIdx.y;
    const float* W = which == 0 ? Wq : (which == 1 ? Wk : Wv);
    unsigned idx = blockIdx.x * 256u + threadIdx.x;   // 0 .. 1024*64*4-1
    int tg = idx & 3;
    unsigned blk = idx >> 2;                          // n*64 + kb
    int n = blk >> 6;
    int kbase = (blk & 63) * 16;
    float a0 = W[(size_t)(kbase + 2 * tg) * ND + n];
    float a1 = W[(size_t)(kbase + 2 * tg + 1) * ND + n];
    float b0 = W[(size_t)(kbase + 2 * tg + 8) * ND + n];
    float b1 = W[(size_t)(kbase + 2 * tg + 9) * ND + n];
    uint2 w2 = make_uint2(packh2(a0, a1), packh2(b0, b1));
    *(uint2*)&g_wt[which][blk * 8 + 2 * tg] = w2;
}

// ---------------------------------------------------------------------------
// Projections: pre-converted fp16 operands, zero in-loop conversion.
// BM=128,BN=128,BK=16; 4 warps, 64x64 warp tiles; cp.async double buffer.
// Per stage: Ah[128][8] + Al[128][8] + Wt[128][8] = 12 KB.
// Per-C-element mma order identical to round 15 => bit-identical outputs.
// ---------------------------------------------------------------------------
__global__ __launch_bounds__(128) void proj_kernel()
{
    __shared__ unsigned sbuf[8256];      // stages at words 0 / 3072; epilogue reuse

    const int which = blockIdx.z;
    const unsigned* Ahg = g_ah[which];
    const unsigned* Alg = g_al[which];
    const unsigned* Wtg = g_wt[which];

    const int tid = threadIdx.x;
    const int lane = tid & 31;
    const int w = tid >> 5;
    const int gid = lane >> 2, tig = lane & 3;
    const int wm = w >> 1, wn = w & 1;
    const int m0 = blockIdx.y * 128, n0 = blockIdx.x * 128;

    const unsigned* ag = Ahg + (size_t)(m0 + tid) * 512;
    const unsigned* lg = Alg + (size_t)(m0 + tid) * 512;
    const unsigned* wg = Wtg + (size_t)(n0 + tid) * 512;

    unsigned sb = (unsigned)__cvta_generic_to_shared(sbuf);
    unsigned ah_dst[2], al_dst[2], wt_dst[2];
    #pragma unroll
    for (int s = 0; s < 2; s++) {
        unsigned base = sb + s * 3072 * 4;
        ah_dst[s] = base + tid * 32;
        al_dst[s] = base + 1024 * 4 + tid * 32;
        wt_dst[s] = base + 2048 * 4 + tid * 32;
    }

    float C[4][8][4];
    #pragma unroll
    for (int i = 0; i < 4; i++)
        #pragma unroll
        for (int j = 0; j < 8; j++)
            #pragma unroll
            for (int e = 0; e < 4; e++) C[i][j][e] = 0.f;

    {
        cp16(ah_dst[0],      ag);
        cp16(ah_dst[0] + 16, ag + 4);
        cp16(al_dst[0],      lg);
        cp16(al_dst[0] + 16, lg + 4);
        cp16(wt_dst[0],      wg);
        cp16(wt_dst[0] + 16, wg + 4);
        CP_COMMIT();
    }

    const int NIT = 64;
    for (int it = 0; it < NIT; it++) {
        CP_WAIT0();
        __syncthreads();

        if (it + 1 < NIT) {
            const int o = (it + 1) * 8;
            const int s = (it + 1) & 1;
            cp16(ah_dst[s],      ag + o);
            cp16(ah_dst[s] + 16, ag + o + 4);
            cp16(al_dst[s],      lg + o);
            cp16(al_dst[s] + 16, lg + o + 4);
            cp16(wt_dst[s],      wg + o);
            cp16(wt_dst[s] + 16, wg + o + 4);
            CP_COMMIT();
        }

        const unsigned* Ahs = sbuf + (it & 1) * 3072;
        const unsigned* Als = Ahs + 1024;
        const unsigned* Wts = Ahs + 2048;

        unsigned ah[4][4], al[4][4], bw[8][2];
        #pragma unroll
        for (int mf = 0; mf < 4; mf++) {
            int r = wm * 64 + mf * 16 + gid;
            uint2 h0 = *(const uint2*)&Ahs[r * 8 + 2 * tig];
            uint2 h1 = *(const uint2*)&Ahs[(r + 8) * 8 + 2 * tig];
            uint2 l0 = *(const uint2*)&Als[r * 8 + 2 * tig];
            uint2 l1 = *(const uint2*)&Als[(r + 8) * 8 + 2 * tig];
            ah[mf][0] = h0.x; ah[mf][1] = h1.x; ah[mf][2] = h0.y; ah[mf][3] = h1.y;
            al[mf][0] = l0.x; al[mf][1] = l1.x; al[mf][2] = l0.y; al[mf][3] = l1.y;
        }
        #pragma unroll
        for (int nf = 0; nf < 8; nf++) {
            int c = wn * 64 + nf * 8 + gid;
            uint2 b = *(const uint2*)&Wts[c * 8 + 2 * tig];
            bw[nf][0] = b.x; bw[nf][1] = b.y;
        }
        #pragma unroll
        for (int mf = 0; mf < 4; mf++)
            #pragma unroll
            for (int nf = 0; nf < 8; nf++) {
                mmah(C[mf][nf], al[mf], bw[nf]);
                mmah(C[mf][nf], ah[mf], bw[nf]);
            }
    }

    unsigned* out = g_scr[which];
    if (which < 2) {
        const float sc = (which == 0) ? QSC : 1.0f;
        #pragma unroll
        for (int mf = 0; mf < 4; mf++) {
            int R = m0 + wm * 64 + mf * 16 + gid;
            #pragma unroll
            for (int half = 0; half < 2; half++) {
                int Rr = R + half * 8;
                int bb = Rr >> 11;
                int s  = Rr & 2047;
                #pragma unroll
                for (int nf = 0; nf < 8; nf++) {
                    int Cc = n0 + wn * 64 + nf * 8 + tig * 2;
                    int hh = Cc >> 6, dd = Cc & 63;
                    int wword = dd >> 1;
                    unsigned* base = out + ((size_t)(bb * NH + hh) * SS + s) * 32;
                    base[SLOT16(wword)] = packh2(C[mf][nf][half * 2 + 0] * sc,
                                                 C[mf][nf][half * 2 + 1] * sc);
                }
            }
        }
    } else {
        // V: [bh][d][SS/2 words], pi key order within 64-groups, slot16 positions
        float (*stg)[129] = (float(*)[129])sbuf;
        #pragma unroll
        for (int ch = 0; ch < 2; ch++) {
            __syncthreads();
            if (wm == ch) {
                #pragma unroll
                for (int mf = 0; mf < 4; mf++)
                    #pragma unroll
                    for (int half = 0; half < 2; half++) {
                        int rr = mf * 16 + half * 8 + gid;
                        #pragma unroll
                        for (int nf = 0; nf < 8; nf++) {
                            int cc = wn * 64 + nf * 8 + tig * 2;
                            stg[rr][cc]     = C[mf][nf][half * 2 + 0];
                            stg[rr][cc + 1] = C[mf][nf][half * 2 + 1];
                        }
                    }
            }
            __syncthreads();
            const int base_s = m0 + ch * 64;
            const int bb = base_s >> 11;
            const int s_loc = base_s & 2047;
            const int grp = s_loc >> 6;
            #pragma unroll
            for (int cc = 0; cc < 32; cc++) {
                int c = w * 32 + cc;
                int hh = (n0 + c) >> 6, dd = (n0 + c) & 63;
                __half* drow = (__half*)(out + ((size_t)(bb * NH + hh) * HD + dd) * (SS / 2)
                                             + (size_t)grp * 32);
                #pragma unroll
                for (int sg = 0; sg < 2; sg++) {
                    int s = sg * 32 + lane;
                    int mm = s & 7;
                    int x = (s & 0x38) | ((mm & 3) << 1) | (mm >> 2);
                    int u = x >> 1, eps = x & 1;
                    drow[SLOT16(u) * 2 + eps] = __float2half_rn(stg[s][c]);
                }
            }
        }
    }
}

// ---------------------------------------------------------------------------
// Flash attention (round-15, unchanged). fp16 m16n8k16 mma, 128-q tile,
// 4 warps x 32 rows, P in registers, cp.async double-buffered K/V.
// ---------------------------------------------------------------------------
__global__ __launch_bounds__(128, 2) void attn_kernel(
    const int* __restrict__ v_mask, const int* __restrict__ q_mask,
    float* __restrict__ out)
{
    extern __shared__ unsigned smu[];
    unsigned* Qp = smu;                  // [128][36]
    unsigned* KV = smu + 128 * 36;       // [2][ K:64*36 | V:64*36 ]
    float* kbb  = (float*)(KV + 4 * 64 * 36);   // [2][64]

    const int tid = threadIdx.x;
    const int lane = tid & 31;
    const int w = tid >> 5;
    const int gid = lane >> 2, tig = lane & 3;
    const int qt = gridDim.x - 1 - blockIdx.x;
    const int bh = blockIdx.y;
    const int b = bh >> 4, h = bh & 15;
    const int q0 = qt * 128;
    const int kt_hi = (q0 + 127) >> 6;
    const int NT = SS / 64;

    const unsigned* Qg = g_scr[0] + (size_t)bh * SS * 32;
    const unsigned* Kg = g_scr[1] + (size_t)bh * SS * 32;
    const unsigned* Vg = g_scr[2] + (size_t)bh * HD * (SS / 2);

    unsigned sb = (unsigned)__cvta_generic_to_shared(smu);
    const int llr = tid >> 1;
    const int lh16 = (tid & 1) * 16;
    unsigned kdst[2], vdst[2];
    #pragma unroll
    for (int s = 0; s < 2; s++) {
        unsigned base = sb + (128 * 36 + s * 2 * 64 * 36) * 4;
        kdst[s] = base + (llr * 36 + lh16) * 4;
        vdst[s] = base + (64 * 36 + llr * 36 + lh16) * 4;
    }

    {
        unsigned qdst = sb + (tid * 36) * 4;
        const unsigned* qsrc = Qg + (size_t)(q0 + tid) * 32;
        #pragma unroll
        for (int j = 0; j < 8; j++)
            cp16(qdst + j * 16, qsrc + j * 4);
        const unsigned* ksrc = Kg + (size_t)llr * 32 + lh16;
        const unsigned* vsrc = Vg + (size_t)llr * (SS / 2) + lh16;
        #pragma unroll
        for (int j = 0; j < 4; j++) {
            cp16(kdst[0] + j * 16, ksrc + j * 4);
            cp16(vdst[0] + j * 16, vsrc + j * 4);
        }
        if (tid < 64) kbb[tid] = v_mask[b * SS + tid] ? 0.f : -CMSK;
        CP_COMMIT();
    }

    const float NEG_INF = __int_as_float(0xff800000);
    float m[2][2] = {{NEG_INF, NEG_INF}, {NEG_INF, NEG_INF}};
    float l[2][2] = {{0.f, 0.f}, {0.f, 0.f}};
    float acc[2][8][4];
    #pragma unroll
    for (int mf = 0; mf < 2; mf++)
        #pragma unroll
        for (int of = 0; of < 8; of++)
            #pragma unroll
            for (int e = 0; e < 4; e++) acc[mf][of][e] = 0.f;

    int deg = 0;
    const int rq = w * 32 + gid;
    const int kap = (gid >> 1) + ((gid & 1) << 2);
    const int qo0 = rq * 36 + tig * 8;
    const int qo1 = (rq + 8) * 36 + tig * 8;
    const int qo2 = (rq + 16) * 36 + tig * 8;
    const int qo3 = (rq + 24) * 36 + tig * 8;

    float rkb = 0.f;

    for (int kt = 0; kt < NT; kt++) {
        if (kt > kt_hi && !deg) { CP_WAIT0(); break; }
        const int k0 = kt * 64;
        const int cur = kt & 1, nxt = cur ^ 1;
        const unsigned* Kp = KV + cur * (2 * 64 * 36);
        const unsigned* Vp = Kp + 64 * 36;
        const float* kb = kbb + cur * 64;
        const bool pf = (kt + 1 < NT);

        CP_WAIT0();
        __syncthreads();

        float sc[2][8][4];
        #pragma unroll
        for (int mf = 0; mf < 2; mf++)
            #pragma unroll
            for (int nf = 0; nf < 8; nf++)
                #pragma unroll
                for (int e = 0; e < 4; e++) sc[mf][nf][e] = 0.f;

        #pragma unroll
        for (int j = 0; j < 2; j++) {
            uint4 a0 = *(const uint4*)&Qp[qo0 + j * 4];
            uint4 a1 = *(const uint4*)&Qp[qo1 + j * 4];
            uint4 a2 = *(const uint4*)&Qp[qo2 + j * 4];
            uint4 a3 = *(const uint4*)&Qp[qo3 + j * 4];
            unsigned Ae0[4] = {a0.x, a1.x, a0.y, a1.y};
            unsigned Ao0[4] = {a0.z, a1.z, a0.w, a1.w};
            unsigned Ae1[4] = {a2.x, a3.x, a2.y, a3.y};
            unsigned Ao1[4] = {a2.z, a3.z, a2.w, a3.w};
            #pragma unroll
            for (int nf = 0; nf < 8; nf++) {
                uint4 bv = *(const uint4*)&Kp[(nf * 8 + kap) * 36 + tig * 8 + j * 4];
                unsigned Be[2] = {bv.x, bv.y};
                unsigned Bo[2] = {bv.z, bv.w};
                mmah(sc[0][nf], Ae0, Be);
                mmah(sc[0][nf], Ao0, Bo);
                mmah(sc[1][nf], Ae1, Be);
                mmah(sc[1][nf], Ao1, Bo);
            }
        }

        if (pf) {
            const int nk0 = k0 + 64;
            const unsigned* ksrc = Kg + (size_t)(nk0 + llr) * 32 + lh16;
            const unsigned* vsrc = Vg + (size_t)llr * (SS / 2) + (nk0 >> 1) + lh16;
            #pragma unroll
            for (int j = 0; j < 4; j++) {
                cp16(kdst[nxt] + j * 16, ksrc + j * 4);
                cp16(vdst[nxt] + j * 16, vsrc + j * 4);
            }
            CP_COMMIT();
            if (tid < 64) rkb = v_mask[b * SS + nk0 + tid] ? 0.f : -CMSK;
        }

        float kb0[8], kb1[8];
        #pragma unroll
        for (int nf = 0; nf < 8; nf++) {
            kb0[nf] = kb[nf * 8 + tig];
            kb1[nf] = kb[nf * 8 + tig + 4];
        }
        #pragma unroll
        for (int mf = 0; mf < 2; mf++)
            #pragma unroll
            for (int i = 0; i < 2; i++) {
                int qg = q0 + rq + mf * 16 + 8 * i;
                float mx = NEG_INF;
                #pragma unroll
                for (int nf = 0; nf < 8; nf++) {
                    float s0 = sc[mf][nf][2 * i + 0] + kb0[nf];
                    float s1 = sc[mf][nf][2 * i + 1] + kb1[nf];
                    if (k0 + nf * 8 + tig > qg)     s0 -= CMSK;
                    if (k0 + nf * 8 + tig + 4 > qg) s1 -= CMSK;
                    sc[mf][nf][2 * i + 0] = s0;
                    sc[mf][nf][2 * i + 1] = s1;
                    mx = fmaxf(mx, fmaxf(s0, s1));
                }
                mx = fmaxf(mx, __shfl_xor_sync(0xffffffffu, mx, 1));
                mx = fmaxf(mx, __shfl_xor_sync(0xffffffffu, mx, 2));
                float nm = fmaxf(m[mf][i], mx);
                float rs = 0.f;
                #pragma unroll
                for (int nf = 0; nf < 8; nf++)
                    #pragma unroll
                    for (int jj = 0; jj < 2; jj++) {
                        float p = ex2(sc[mf][nf][2 * i + jj] - nm);
                        rs += p;
                        sc[mf][nf][2 * i + jj] = p;
                    }
                rs += __shfl_xor_sync(0xffffffffu, rs, 1);
                rs += __shfl_xor_sync(0xffffffffu, rs, 2);
                float alpha = ex2(m[mf][i] - nm);
                l[mf][i] = l[mf][i] * alpha + rs;
                m[mf][i] = nm;
                #pragma unroll
                for (int of = 0; of < 8; of++) {
                    acc[mf][of][2 * i + 0] *= alpha;
                    acc[mf][of][2 * i + 1] *= alpha;
                }
            }

        unsigned Pw[2][4][4];
        #pragma unroll
        for (int mf = 0; mf < 2; mf++)
            #pragma unroll
            for (int kk = 0; kk < 4; kk++) {
                Pw[mf][kk][0] = packh2(sc[mf][2 * kk][0],     sc[mf][2 * kk][1]);
                Pw[mf][kk][1] = packh2(sc[mf][2 * kk][2],     sc[mf][2 * kk][3]);
                Pw[mf][kk][2] = packh2(sc[mf][2 * kk + 1][0], sc[mf][2 * kk + 1][1]);
                Pw[mf][kk][3] = packh2(sc[mf][2 * kk + 1][2], sc[mf][2 * kk + 1][3]);
            }

        #pragma unroll
        for (int of = 0; of < 8; of++) {
            const unsigned* vb = &Vp[(of * 8 + gid) * 36 + tig * 8];
            uint4 v0 = *(const uint4*)(vb);
            uint4 v1 = *(const uint4*)(vb + 4);
            unsigned B0[2] = {v0.x, v0.y};
            unsigned B1[2] = {v0.z, v0.w};
            unsigned B2[2] = {v1.x, v1.y};
            unsigned B3[2] = {v1.z, v1.w};
            #pragma unroll
            for (int mf = 0; mf < 2; mf++) {
                mmah(acc[mf][of], Pw[mf][0], B0);
                mmah(acc[mf][of], Pw[mf][1], B1);
                mmah(acc[mf][of], Pw[mf][2], B2);
                mmah(acc[mf][of], Pw[mf][3], B3);
            }
        }

        if (pf && tid < 64) kbb[nxt * 64 + tid] = rkb;

        if (kt == kt_hi)
            deg = __syncthreads_or((m[0][0] < -1e10f) || (m[0][1] < -1e10f) ||
                                   (m[1][0] < -1e10f) || (m[1][1] < -1e10f));
    }

    #pragma unroll
    for (int mf = 0; mf < 2; mf++)
        #pragma unroll
        for (int i = 0; i < 2; i++) {
            int qg = q0 + rq + mf * 16 + 8 * i;
            float qm = (float)q_mask[b * SS + qg];
            float f = qm / l[mf][i];
            #pragma unroll
            for (int of = 0; of < 8; of++) {
                float2 o = make_float2(acc[mf][of][2 * i + 0] * f, acc[mf][of][2 * i + 1] * f);
                *(float2*)(out + ((size_t)b * SS + qg) * ND + h * HD + of * 8 + tig * 2) = o;
            }
        }
}

// ---------------------------------------------------------------------------
extern "C" void kernel_launch(void* const* d_in, const int* in_sizes, int n_in,
                              void* d_out, int out_size)
{
    const float* q  = (const float*)d_in[0];
    const float* k  = (const float*)d_in[1];
    const float* v  = (const float*)d_in[2];
    const int* vmask = (const int*)d_in[3];
    const int* qmask = (const int*)d_in[4];
    const float* Wq = (const float*)d_in[5];
    const float* Wk = (const float*)d_in[6];
    const float* Wv = (const float*)d_in[7];
    float* out = (float*)d_out;

    const int smem_attn = (128 * 36 + 4 * 64 * 36 + 2 * 64) * 4;   // 55,808 B
    cudaFuncSetAttribute(attn_kernel, cudaFuncAttributeMaxDynamicSharedMemorySize, smem_attn);

    dim3 ga_prep_a(4096 * 512 / 256, 3);     // 8192 x 3
    prep_a<<<ga_prep_a, 256>>>(q, k, v);
    dim3 ga_prep_w(1024 * 256 / 256, 3);     // 1024 x 3
    prep_w<<<ga_prep_w, 256>>>(Wq, Wk, Wv);

    dim3 gp(ND / 128, (BB * SS) / 128, 3);   // (8, 32, 3)
    proj_kernel<<<gp, 128>>>();

    dim3 ga(SS / 128, BB * NH);              // (16, 32)
    attn_kernel<<<ga, 128, smem_attn>>>(vmask, qmask, out);
}